// round 15
// baseline (speedup 1.0000x reference)
#include <cuda_runtime.h>
#include <cuda_fp16.h>
#include <cstdint>
#include <cstddef>

// ---------------- problem constants ----------------
#define BATCH 16
#define NQ    512
#define NK    1024
#define DH    128
#define HEADS 8
#define BH    (BATCH*HEADS)        // 128
#define SC2   0.12751741254364243f // (1/sqrt(128)) * log2(e)  -- folded into Wq/bq
#define ONESW 0x3C003C00u          // fp16 (1.0, 1.0)

#define TRP 136
#define PRJ_BYTES ((128*80 + 128*80)*4)   // 81920

// flash smem layout (words): Y 2x(64x80), P 2x(128x48)
#define FLY0 0
#define FLY1 (64*80)
#define FLP0 (2*64*80)
#define FLP1 (FLP0 + 128*48)
#define FLW  (FLP1 + 128*48)
#define FL_BYTES (FLW*4)           // 90112

// ---------------- device scratch (fp16, perm32 along K dim) ----------------
__device__ __half g_qh [8192*DH];
__device__ __half g_kh [16384*DH];
__device__ __half g_Wqh[1024*DH];
__device__ __half g_Wkh[1024*DH];
__device__ __half g_Wph[1024*DH];
__device__ __half g_Wgh[1024*DH];
__device__ __half g_u  [(size_t)BH*NQ*DH];      // pre-scaled by SC2
__device__ __half g_v  [(size_t)BH*NK*DH];
__device__ __half g_pT [(size_t)BH*DH*NK];
__device__ __half g_gT [(size_t)BH*DH*NQ];
__device__ __half g_Pmid[(size_t)BATCH*NQ*HEADS*DH];
__device__ __half g_Dmid[(size_t)BATCH*NK*HEADS*DH];
__device__ __half g_Wo1h[128*1024];
__device__ __half g_Wo2h[128*1024];

// ---------------- helpers ----------------
__device__ __forceinline__ uint32_t packh2(float a, float b){
    __half2 h = __floats2half2_rn(a, b);
    return *reinterpret_cast<uint32_t*>(&h);
}
__device__ __forceinline__ uint32_t ex2h2(uint32_t x){
    uint32_t r;
    asm("ex2.approx.f16x2 %0, %1;" : "=r"(r) : "r"(x));
    return r;
}
__device__ __forceinline__ void mma16h(float (&c)[4], uint32_t a0, uint32_t a1, uint32_t a2, uint32_t a3,
                                       uint32_t b0, uint32_t b1){
    asm volatile("mma.sync.aligned.m16n8k16.row.col.f32.f16.f16.f32 "
        "{%0,%1,%2,%3}, {%4,%5,%6,%7}, {%8,%9}, {%0,%1,%2,%3};"
        : "+f"(c[0]),"+f"(c[1]),"+f"(c[2]),"+f"(c[3])
        : "r"(a0),"r"(a1),"r"(a2),"r"(a3), "r"(b0),"r"(b1));
}
__device__ __forceinline__ void cpa16(uint32_t dst_shared, const void* src){
    asm volatile("cp.async.cg.shared.global [%0], [%1], 16;" :: "r"(dst_shared), "l"(src));
}
__device__ __forceinline__ void cpa_commit(){ asm volatile("cp.async.commit_group;"); }
__device__ __forceinline__ void cpa_wait0(){ asm volatile("cp.async.wait_group 0;"); }

// perm32: word w of a 32-half chunk = j*4+hi*2+s holds halves (s*16+hi*8+2j, +1)
__device__ __forceinline__ int perm_w(int h32){
    int s = (h32 >> 4) & 1, hi = (h32 >> 3) & 1, j = (h32 & 7) >> 1;
    return j*4 + hi*2 + s;
}

// ================= conversion kernel: fp32 -> fp16 perm32 =================
__global__ void __launch_bounds__(256)
conv_all_kernel(const float* __restrict__ q, const float* __restrict__ k,
                const float* __restrict__ Wq, const float* __restrict__ Wk,
                const float* __restrict__ Wp, const float* __restrict__ Wg,
                const float* __restrict__ Wo1, const float* __restrict__ Wo2){
    int t = blockIdx.x*256 + threadIdx.x;
    int seg = blockIdx.y;
    const float* src; uint32_t* dst; int nwords;
    switch (seg){
        case 0: src = q;   dst = (uint32_t*)g_qh;  nwords = 8192*64;  break;
        case 1: src = k;   dst = (uint32_t*)g_kh;  nwords = 16384*64; break;
        case 2: src = Wq;  dst = (uint32_t*)g_Wqh; nwords = 1024*64;  break;
        case 3: src = Wk;  dst = (uint32_t*)g_Wkh; nwords = 1024*64;  break;
        case 4: src = Wp;  dst = (uint32_t*)g_Wph; nwords = 1024*64;  break;
        case 5: src = Wg;  dst = (uint32_t*)g_Wgh; nwords = 1024*64;  break;
        case 6: src = Wo1; dst = (uint32_t*)g_Wo1h; nwords = 128*512; break;
        default:src = Wo2; dst = (uint32_t*)g_Wo2h; nwords = 128*512; break;
    }
    if (t >= nwords) return;
    int r, w9, rowfloats;
    if (seg < 6){ r = t >> 6; w9 = t & 63;  rowfloats = 128;  }
    else        { r = t >> 9; w9 = t & 511; rowfloats = 1024; }
    int chunk = w9 >> 4, wd = w9 & 15;
    int j = wd >> 2, hi = (wd >> 1) & 1, s = wd & 1;
    int k0 = chunk*32 + s*16 + hi*8 + 2*j;
    const float* sp = src + (size_t)r*rowfloats + k0;
    float sc = (seg == 2) ? SC2 : 1.0f;
    dst[t] = packh2(sp[0]*sc, sp[1]*sc);
}

// ================= input projections (R11 independent version) =================
__global__ void __launch_bounds__(256)
proj_kernel(const float* __restrict__ bq, const float* __restrict__ bk,
            const float* __restrict__ bp, const float* __restrict__ bg){
    extern __shared__ uint32_t smw[];
    const int bx = blockIdx.x;
    const bool isK = (bx >= 64);
    const int m0 = (isK ? bx - 64 : bx) * 128;
    const int trans = blockIdx.y >> 3;
    const int n0 = (blockIdx.y & 7) * 128;
    const __half* Xh  = isK ? g_kh : g_qh;
    const __half* Wh  = trans ? (isK ? g_Wph : g_Wgh) : (isK ? g_Wkh : g_Wqh);
    const float* bias = trans ? (isK ? bp : bg) : (isK ? bk : bq);
    __half* Yout      = trans ? (isK ? g_pT : g_gT) : (isK ? g_v : g_u);
    const float bsc   = (!isK && !trans) ? SC2 : 1.0f;
    const int Nrows   = isK ? NK : NQ;
    const int nshift  = isK ? 10 : 9;
    const int tid = threadIdx.x, w = tid >> 5, lane = tid & 31;
    const int g = lane >> 2, tq = lane & 3;
    const int wm = w >> 1, wn = w & 1;

    uint32_t sx = (uint32_t)__cvta_generic_to_shared(smw);
    uint32_t sw = sx + 10240*4;
    const uint32_t* Xw = (const uint32_t*)Xh + (size_t)m0*64;
    const uint32_t* Ww = (const uint32_t*)Wh + (size_t)n0*64;
    #pragma unroll
    for (int i = 0; i < 8; i++){
        int id = tid + i*256;
        int r = id >> 4, wq = id & 15;
        cpa16(sx + (r*80 + wq*4)*4, Xw + (size_t)r*64 + wq*4);
        cpa16(sw + (r*80 + wq*4)*4, Ww + (size_t)r*64 + wq*4);
    }
    cpa_commit();
    cpa_wait0();
    __syncthreads();

    float acc[2][8][4] = {};
    const uint32_t* Xs = smw;
    const uint32_t* Ws = smw + 10240;
    #pragma unroll
    for (int kk = 0; kk < 4; kk++){
        uint4 xa[2], xb[2];
        #pragma unroll
        for (int mi = 0; mi < 2; mi++){
            xa[mi] = *(const uint4*)(Xs + (wm*32+mi*16+g)*80 + kk*16 + tq*4);
            xb[mi] = *(const uint4*)(Xs + (wm*32+mi*16+g+8)*80 + kk*16 + tq*4);
        }
        #pragma unroll
        for (int ni = 0; ni < 8; ni++){
            uint4 bb = *(const uint4*)(Ws + (wn*64+ni*8+g)*80 + kk*16 + tq*4);
            #pragma unroll
            for (int mi = 0; mi < 2; mi++){
                mma16h(acc[mi][ni], xa[mi].x, xb[mi].x, xa[mi].z, xb[mi].z, bb.x, bb.z);
                mma16h(acc[mi][ni], xa[mi].y, xb[mi].y, xa[mi].w, xb[mi].w, bb.y, bb.w);
            }
        }
    }
    __syncthreads();

    const int h = n0 >> 7;
    if (!trans){
        uint32_t* Yw = (uint32_t*)Yout;
        #pragma unroll
        for (int mi = 0; mi < 2; mi++)
        #pragma unroll
        for (int hh = 0; hh < 2; hh++)
        #pragma unroll
        for (int ni = 0; ni < 8; ni++){
            int row = m0 + wm*32 + mi*16 + g + hh*8;
            int d = wn*64 + ni*8 + tq*2;
            int b = row >> nshift, n = row - (b << nshift);
            int wrd = ((d >> 5) << 4) + perm_w(d & 31);
            Yw[(size_t)((b*HEADS + h)*Nrows + n)*64 + wrd] =
                packh2(acc[mi][ni][hh*2] + bias[n0+d]*bsc, acc[mi][ni][hh*2+1] + bias[n0+d+1]*bsc);
        }
    } else {
        float* tr = (float*)smw;
        #pragma unroll
        for (int mi = 0; mi < 2; mi++)
        #pragma unroll
        for (int hh = 0; hh < 2; hh++)
        #pragma unroll
        for (int ni = 0; ni < 8; ni++)
        #pragma unroll
        for (int cc = 0; cc < 2; cc++){
            int rl = wm*32 + mi*16 + g + hh*8;
            int cl = wn*64 + ni*8 + tq*2 + cc;
            tr[cl*TRP + rl] = acc[mi][ni][hh*2+cc] + bias[n0+cl];
        }
        __syncthreads();
        int b = m0 >> nshift, nloc0 = m0 - (b << nshift);
        int cl = tid >> 1, half = tid & 1;
        uint32_t* Yw = (uint32_t*)Yout;
        uint32_t* dstrow = Yw + ((size_t)(b*HEADS + h)*DH + cl)*(size_t)(Nrows>>1) + (nloc0>>1);
        #pragma unroll
        for (int c2 = 0; c2 < 2; c2++){
            int chunk = half*2 + c2;
            const float* src = tr + cl*TRP + chunk*32;
            uint32_t wds[16];
            #pragma unroll
            for (int wd = 0; wd < 16; wd++){
                int j = wd >> 2, hi = (wd >> 1) & 1, s = wd & 1;
                int h0 = s*16 + hi*8 + 2*j;
                wds[wd] = packh2(src[h0], src[h0+1]);
            }
            uint32_t* dst = dstrow + chunk*16;
            #pragma unroll
            for (int qq = 0; qq < 4; qq++)
                ((uint4*)dst)[qq] = make_uint4(wds[qq*4], wds[qq*4+1], wds[qq*4+2], wds[qq*4+3]);
        }
    }
}

// ================= merged fused flash kernel (64-key stages, split mma chains) =================
__global__ void __launch_bounds__(256, 2)
flash_kernel(){
    extern __shared__ uint32_t smw[];
    const __half *X, *Y, *VT; __half* Mid; int M, Nk, mb;
    if (blockIdx.x < 4){ X=g_u; Y=g_v; VT=g_pT; Mid=g_Pmid; M=NQ; Nk=NK; mb=blockIdx.x; }
    else               { X=g_v; Y=g_u; VT=g_gT; Mid=g_Dmid; M=NK; Nk=NQ; mb=blockIdx.x-4; }
    const int bh = blockIdx.y;
    const int m0 = mb * 128;
    const int tid = threadIdx.x, w = tid >> 5, lane = tid & 31;
    const int g = lane >> 2, tq = lane & 3;
    const int Nk2 = Nk >> 1;
    const int NT = Nk >> 6;
    const uint32_t* Xw = (const uint32_t*)(X + ((size_t)bh*M + m0)*DH);
    const uint32_t* Yw = (const uint32_t*)(Y + (size_t)bh*Nk*DH);
    const uint32_t* Vw = (const uint32_t*)(VT + (size_t)bh*DH*Nk);
    uint32_t sbase = (uint32_t)__cvta_generic_to_shared(smw);

    uint4 xa[4], xb[4];
    {
        const uint32_t* Xr = Xw + (size_t)(w*16 + g)*64 + tq*4;
        #pragma unroll
        for (int kk2 = 0; kk2 < 4; kk2++){
            xa[kk2] = *(const uint4*)(Xr + kk2*16);
            xb[kk2] = *(const uint4*)(Xr + 8*64 + kk2*16);
        }
    }

    const int yr = tid >> 4, ywq = tid & 15;
    const int pr2 = tid >> 3, pch = tid & 7;

    {
        #pragma unroll
        for (int i = 0; i < 4; i++){
            int r = yr + i*16;
            cpa16(sbase + (FLY0 + r*80 + ywq*4)*4, Yw + (size_t)r*64 + ywq*4);
        }
        #pragma unroll
        for (int i = 0; i < 4; i++){
            int r = pr2 + i*32;
            cpa16(sbase + (FLP0 + r*48 + pch*4)*4, Vw + (size_t)r*Nk2 + pch*4);
        }
        cpa_commit();
    }

    float acc[16][4] = {};
    float acc_rs[4] = {};
    int buf = 0;

    for (int kt = 0; kt < NT; kt++){
        cpa_wait0();
        __syncthreads();

        if (kt + 1 < NT){
            int yb = buf ? FLY0 : FLY1;
            int pb = buf ? FLP0 : FLP1;
            #pragma unroll
            for (int i = 0; i < 4; i++){
                int r = yr + i*16;
                cpa16(sbase + (yb + r*80 + ywq*4)*4, Yw + (size_t)((kt+1)*64 + r)*64 + ywq*4);
            }
            #pragma unroll
            for (int i = 0; i < 4; i++){
                int r = pr2 + i*32;
                cpa16(sbase + (pb + r*48 + pch*4)*4, Vw + (size_t)r*Nk2 + (kt+1)*32 + pch*4);
            }
            cpa_commit();
        }

        const uint32_t* Yb = smw + (buf ? FLY1 : FLY0);
        const uint32_t* Pb = smw + (buf ? FLP1 : FLP0);

        #pragma unroll
        for (int sub = 0; sub < 2; sub++){
            const uint32_t* Ys = Yb + sub*32*80;

            // gemm1 (split chains: two 4-deep halves per ni) + softmax
            uint32_t eh[4][2];
            #pragma unroll
            for (int ni = 0; ni < 4; ni++){
                float cs[4] = {0.f, 0.f, 0.f, 0.f};
                float cs2[4] = {0.f, 0.f, 0.f, 0.f};
                #pragma unroll
                for (int kk2 = 0; kk2 < 2; kk2++){
                    uint4 r = *(const uint4*)(Ys + (ni*8 + g)*80 + kk2*16 + tq*4);
                    mma16h(cs, xa[kk2].x, xb[kk2].x, xa[kk2].z, xb[kk2].z, r.x, r.z);
                    mma16h(cs, xa[kk2].y, xb[kk2].y, xa[kk2].w, xb[kk2].w, r.y, r.w);
                }
                #pragma unroll
                for (int kk2 = 2; kk2 < 4; kk2++){
                    uint4 r = *(const uint4*)(Ys + (ni*8 + g)*80 + kk2*16 + tq*4);
                    mma16h(cs2, xa[kk2].x, xb[kk2].x, xa[kk2].z, xb[kk2].z, r.x, r.z);
                    mma16h(cs2, xa[kk2].y, xb[kk2].y, xa[kk2].w, xb[kk2].w, r.y, r.w);
                }
                eh[ni][0] = ex2h2(packh2(cs[0]+cs2[0], cs[1]+cs2[1]));
                eh[ni][1] = ex2h2(packh2(cs[2]+cs2[2], cs[3]+cs2[3]));
            }

            mma16h(acc_rs, eh[0][0], eh[0][1], eh[1][0], eh[1][1], ONESW, ONESW);
            mma16h(acc_rs, eh[2][0], eh[2][1], eh[3][0], eh[3][1], ONESW, ONESW);

            #pragma unroll
            for (int n2 = 0; n2 < 16; n2++){
                uint4 r = *(const uint4*)(Pb + (n2*8 + g)*48 + sub*16 + tq*4);
                mma16h(acc[n2], eh[0][0], eh[0][1], eh[1][0], eh[1][1], r.x, r.z);
                mma16h(acc[n2], eh[2][0], eh[2][1], eh[3][0], eh[3][1], r.y, r.w);
            }
        }
        buf ^= 1;
    }

    float i0 = 1.0f / acc_rs[0], i1 = 1.0f / acc_rs[2];
    int b = bh >> 3, h = bh & 7;
    int mg = m0 + w*16 + g;
    uint32_t* o0 = (uint32_t*)Mid + (((size_t)(b*M + mg    )*HEADS + h) << 6);
    uint32_t* o8 = (uint32_t*)Mid + (((size_t)(b*M + mg + 8)*HEADS + h) << 6);
    #pragma unroll
    for (int n2 = 0; n2 < 16; n2++){
        int col = n2*8 + 2*tq;
        int wrd = ((col >> 5) << 4) + perm_w(col & 31);
        o0[wrd] = packh2(acc[n2][0]*i0, acc[n2][1]*i0);
        o8[wrd] = packh2(acc[n2][2]*i1, acc[n2][3]*i1);
    }
}

// ================= merged output projection (fp16 cp.async, 2-stage, 3 CTAs/SM) =================
__global__ void __launch_bounds__(256, 3)
outproj_kernel(const float* __restrict__ bo1, const float* __restrict__ bo2,
               float* __restrict__ out){
    __shared__ uint32_t As[2][128*16];
    __shared__ uint32_t Bs[2][64*16];
    const int bx = blockIdx.x;
    const bool isD = (bx >= 64);
    const int m0 = (isD ? bx - 64 : bx) * 128;
    const int n0 = blockIdx.y * 64;
    const __half* Xh = isD ? g_Dmid : g_Pmid;
    const __half* Wh = isD ? g_Wo2h : g_Wo1h;
    const float* bias = isD ? bo2 : bo1;
    float* outp = out + (isD ? (size_t)BATCH*NQ*DH : 0);
    const int tid = threadIdx.x, w = tid >> 5, lane = tid & 31;
    const int g = lane >> 2, tq = lane & 3;
    const int wm = w >> 1, wn = w & 1;
    const uint32_t* Xw = (const uint32_t*)Xh + (size_t)m0*512;
    const uint32_t* Ww = (const uint32_t*)Wh + (size_t)n0*512;
    uint32_t sa = (uint32_t)__cvta_generic_to_shared(&As[0][0]);
    uint32_t sb = (uint32_t)__cvta_generic_to_shared(&Bs[0][0]);

    float c[2][4][4] = {};
    {
        #pragma unroll
        for (int i = 0; i < 2; i++){
            int u = tid + i*256; int r = u >> 2, q = u & 3;
            cpa16(sa + (r*16 + q*4)*4, Xw + (size_t)r*512 + q*4);
        }
        { int r = tid >> 2, q = tid & 3;
          cpa16(sb + (r*16 + q*4)*4, Ww + (size_t)r*512 + q*4); }
        cpa_commit();
    }

    int buf = 0;
    for (int kt = 0; kt < 32; kt++){
        cpa_wait0();
        __syncthreads();
        if (kt + 1 < 32){
            int nb = buf ^ 1;
            #pragma unroll
            for (int i = 0; i < 2; i++){
                int u = tid + i*256; int r = u >> 2, q = u & 3;
                cpa16(sa + (nb*2048 + r*16 + q*4)*4, Xw + (size_t)r*512 + (kt+1)*16 + q*4);
            }
            { int r = tid >> 2, q = tid & 3;
              cpa16(sb + (nb*1024 + r*16 + q*4)*4, Ww + (size_t)r*512 + (kt+1)*16 + q*4); }
            cpa_commit();
        }
        const uint32_t* A = &As[buf][0];
        const uint32_t* B = &Bs[buf][0];
        uint4 xa[2], xb[2];
        #pragma unroll
        for (int mi = 0; mi < 2; mi++){
            xa[mi] = *(const uint4*)(A + (wm*32+mi*16+g)*16 + tq*4);
            xb[mi] = *(const uint4*)(A + (wm*32+mi*16+g+8)*16 + tq*4);
        }
        #pragma unroll
        for (int ni = 0; ni < 4; ni++){
            uint4 bb = *(const uint4*)(B + (wn*32+ni*8+g)*16 + tq*4);
            #pragma unroll
            for (int mi = 0; mi < 2; mi++){
                mma16h(c[mi][ni], xa[mi].x, xb[mi].x, xa[mi].z, xb[mi].z, bb.x, bb.z);
                mma16h(c[mi][ni], xa[mi].y, xb[mi].y, xa[mi].w, xb[mi].w, bb.y, bb.w);
            }
        }
        buf ^= 1;
    }

    #pragma unroll
    for (int mi=0;mi<2;mi++)
    #pragma unroll
    for (int hh=0;hh<2;hh++)
    #pragma unroll
    for (int ni=0;ni<4;ni++)
    #pragma unroll
    for (int cc=0;cc<2;cc++){
        int row = m0 + wm*32 + mi*16 + g + hh*8;
        int col = n0 + wn*32 + ni*8 + tq*2 + cc;
        outp[((size_t)row << 7) + col] = c[mi][ni][hh*2+cc] + bias[col];
    }
}

// ---------------- launch ----------------
extern "C" void kernel_launch(void* const* d_in, const int* in_sizes, int n_in,
                              void* d_out, int out_size){
    const float* queries = (const float*)d_in[0];
    const float* keys    = (const float*)d_in[1];
    const float* Wq  = (const float*)d_in[2];
    const float* bq  = (const float*)d_in[3];
    const float* Wk  = (const float*)d_in[4];
    const float* bk  = (const float*)d_in[5];
    const float* Wp  = (const float*)d_in[6];
    const float* bp  = (const float*)d_in[7];
    const float* Wg  = (const float*)d_in[8];
    const float* bg  = (const float*)d_in[9];
    const float* Wo1 = (const float*)d_in[10];
    const float* bo1 = (const float*)d_in[11];
    const float* Wo2 = (const float*)d_in[12];
    const float* bo2 = (const float*)d_in[13];
    float* out = (float*)d_out;

    cudaFuncSetAttribute(proj_kernel,  cudaFuncAttributeMaxDynamicSharedMemorySize, PRJ_BYTES);
    cudaFuncSetAttribute(flash_kernel, cudaFuncAttributeMaxDynamicSharedMemorySize, FL_BYTES);

    conv_all_kernel<<<dim3(4096, 8), 256>>>(queries, keys, Wq, Wk, Wp, Wg, Wo1, Wo2);

    proj_kernel<<<dim3(192, 16), 256, PRJ_BYTES>>>(bq, bk, bp, bg);

    flash_kernel<<<dim3(12, BH), 256, FL_BYTES>>>();

    outproj_kernel<<<dim3(192, 2), 256>>>(bo1, bo2, out);
}

// round 16
// speedup vs baseline: 1.0307x; 1.0307x over previous
#include <cuda_runtime.h>
#include <cuda_fp16.h>
#include <cstdint>
#include <cstddef>

// ---------------- problem constants ----------------
#define BATCH 16
#define NQ    512
#define NK    1024
#define DH    128
#define HEADS 8
#define BH    (BATCH*HEADS)        // 128
#define SC2   0.12751741254364243f // (1/sqrt(128)) * log2(e)  -- folded into Wq/bq
#define ONESW 0x3C003C00u          // fp16 (1.0, 1.0)

#define TRP 136
#define PRJ_BYTES ((128*80 + 128*80)*4)   // 81920

// flash smem layout (words): Y 2x(64x80), P 2x(128x48)
#define FLY0 0
#define FLY1 (64*80)
#define FLP0 (2*64*80)
#define FLP1 (FLP0 + 128*48)
#define FLW  (FLP1 + 128*48)
#define FL_BYTES (FLW*4)           // 90112

// ---------------- device scratch (fp16, perm32 along K dim) ----------------
__device__ __half g_qh [8192*DH];
__device__ __half g_kh [16384*DH];
__device__ __half g_Wqh[1024*DH];
__device__ __half g_Wkh[1024*DH];
__device__ __half g_Wph[1024*DH];
__device__ __half g_Wgh[1024*DH];
__device__ __half g_u  [(size_t)BH*NQ*DH];      // pre-scaled by SC2
__device__ __half g_v  [(size_t)BH*NK*DH];
__device__ __half g_pT [(size_t)BH*DH*NK];
__device__ __half g_gT [(size_t)BH*DH*NQ];
__device__ __half g_Pmid[(size_t)BATCH*NQ*HEADS*DH];
__device__ __half g_Dmid[(size_t)BATCH*NK*HEADS*DH];
__device__ __half g_Wo1h[128*1024];
__device__ __half g_Wo2h[128*1024];

// ---------------- helpers ----------------
__device__ __forceinline__ uint32_t packh2(float a, float b){
    __half2 h = __floats2half2_rn(a, b);
    return *reinterpret_cast<uint32_t*>(&h);
}
__device__ __forceinline__ uint32_t ex2h2(uint32_t x){
    uint32_t r;
    asm("ex2.approx.f16x2 %0, %1;" : "=r"(r) : "r"(x));
    return r;
}
__device__ __forceinline__ void mma16h(float (&c)[4], uint32_t a0, uint32_t a1, uint32_t a2, uint32_t a3,
                                       uint32_t b0, uint32_t b1){
    asm volatile("mma.sync.aligned.m16n8k16.row.col.f32.f16.f16.f32 "
        "{%0,%1,%2,%3}, {%4,%5,%6,%7}, {%8,%9}, {%0,%1,%2,%3};"
        : "+f"(c[0]),"+f"(c[1]),"+f"(c[2]),"+f"(c[3])
        : "r"(a0),"r"(a1),"r"(a2),"r"(a3), "r"(b0),"r"(b1));
}
__device__ __forceinline__ void cpa16(uint32_t dst_shared, const void* src){
    asm volatile("cp.async.cg.shared.global [%0], [%1], 16;" :: "r"(dst_shared), "l"(src));
}
__device__ __forceinline__ void cpa_commit(){ asm volatile("cp.async.commit_group;"); }
__device__ __forceinline__ void cpa_wait0(){ asm volatile("cp.async.wait_group 0;"); }

// perm32: word w of a 32-half chunk = j*4+hi*2+s holds halves (s*16+hi*8+2j, +1)
__device__ __forceinline__ int perm_w(int h32){
    int s = (h32 >> 4) & 1, hi = (h32 >> 3) & 1, j = (h32 & 7) >> 1;
    return j*4 + hi*2 + s;
}

// ================= conversion kernel: fp32 -> fp16 perm32 =================
__global__ void __launch_bounds__(256)
conv_all_kernel(const float* __restrict__ q, const float* __restrict__ k,
                const float* __restrict__ Wq, const float* __restrict__ Wk,
                const float* __restrict__ Wp, const float* __restrict__ Wg,
                const float* __restrict__ Wo1, const float* __restrict__ Wo2){
    int t = blockIdx.x*256 + threadIdx.x;
    int seg = blockIdx.y;
    const float* src; uint32_t* dst; int nwords;
    switch (seg){
        case 0: src = q;   dst = (uint32_t*)g_qh;  nwords = 8192*64;  break;
        case 1: src = k;   dst = (uint32_t*)g_kh;  nwords = 16384*64; break;
        case 2: src = Wq;  dst = (uint32_t*)g_Wqh; nwords = 1024*64;  break;
        case 3: src = Wk;  dst = (uint32_t*)g_Wkh; nwords = 1024*64;  break;
        case 4: src = Wp;  dst = (uint32_t*)g_Wph; nwords = 1024*64;  break;
        case 5: src = Wg;  dst = (uint32_t*)g_Wgh; nwords = 1024*64;  break;
        case 6: src = Wo1; dst = (uint32_t*)g_Wo1h; nwords = 128*512; break;
        default:src = Wo2; dst = (uint32_t*)g_Wo2h; nwords = 128*512; break;
    }
    if (t >= nwords) return;
    int r, w9, rowfloats;
    if (seg < 6){ r = t >> 6; w9 = t & 63;  rowfloats = 128;  }
    else        { r = t >> 9; w9 = t & 511; rowfloats = 1024; }
    int chunk = w9 >> 4, wd = w9 & 15;
    int j = wd >> 2, hi = (wd >> 1) & 1, s = wd & 1;
    int k0 = chunk*32 + s*16 + hi*8 + 2*j;
    const float* sp = src + (size_t)r*rowfloats + k0;
    float sc = (seg == 2) ? SC2 : 1.0f;
    dst[t] = packh2(sp[0]*sc, sp[1]*sc);
}

// ================= input projections (fp16 cp.async GEMM) =================
__global__ void __launch_bounds__(256)
proj_kernel(const float* __restrict__ bq, const float* __restrict__ bk,
            const float* __restrict__ bp, const float* __restrict__ bg){
    extern __shared__ uint32_t smw[];
    const int bx = blockIdx.x;
    const bool isK = (bx >= 64);
    const int m0 = (isK ? bx - 64 : bx) * 128;
    const int trans = blockIdx.y >> 3;
    const int n0 = (blockIdx.y & 7) * 128;
    const __half* Xh  = isK ? g_kh : g_qh;
    const __half* Wh  = trans ? (isK ? g_Wph : g_Wgh) : (isK ? g_Wkh : g_Wqh);
    const float* bias = trans ? (isK ? bp : bg) : (isK ? bk : bq);
    __half* Yout      = trans ? (isK ? g_pT : g_gT) : (isK ? g_v : g_u);
    const float bsc   = (!isK && !trans) ? SC2 : 1.0f;
    const int Nrows   = isK ? NK : NQ;
    const int nshift  = isK ? 10 : 9;
    const int tid = threadIdx.x, w = tid >> 5, lane = tid & 31;
    const int g = lane >> 2, tq = lane & 3;
    const int wm = w >> 1, wn = w & 1;

    uint32_t sx = (uint32_t)__cvta_generic_to_shared(smw);
    uint32_t sw = sx + 10240*4;
    const uint32_t* Xw = (const uint32_t*)Xh + (size_t)m0*64;
    const uint32_t* Ww = (const uint32_t*)Wh + (size_t)n0*64;
    #pragma unroll
    for (int i = 0; i < 8; i++){
        int id = tid + i*256;
        int r = id >> 4, wq = id & 15;
        cpa16(sx + (r*80 + wq*4)*4, Xw + (size_t)r*64 + wq*4);
        cpa16(sw + (r*80 + wq*4)*4, Ww + (size_t)r*64 + wq*4);
    }
    cpa_commit();
    cpa_wait0();
    __syncthreads();

    float acc[2][8][4] = {};
    const uint32_t* Xs = smw;
    const uint32_t* Ws = smw + 10240;
    #pragma unroll
    for (int kk = 0; kk < 4; kk++){
        uint4 xa[2], xb[2];
        #pragma unroll
        for (int mi = 0; mi < 2; mi++){
            xa[mi] = *(const uint4*)(Xs + (wm*32+mi*16+g)*80 + kk*16 + tq*4);
            xb[mi] = *(const uint4*)(Xs + (wm*32+mi*16+g+8)*80 + kk*16 + tq*4);
        }
        #pragma unroll
        for (int ni = 0; ni < 8; ni++){
            uint4 bb = *(const uint4*)(Ws + (wn*64+ni*8+g)*80 + kk*16 + tq*4);
            #pragma unroll
            for (int mi = 0; mi < 2; mi++){
                mma16h(acc[mi][ni], xa[mi].x, xb[mi].x, xa[mi].z, xb[mi].z, bb.x, bb.z);
                mma16h(acc[mi][ni], xa[mi].y, xb[mi].y, xa[mi].w, xb[mi].w, bb.y, bb.w);
            }
        }
    }
    __syncthreads();

    const int h = n0 >> 7;
    if (!trans){
        uint32_t* Yw = (uint32_t*)Yout;
        #pragma unroll
        for (int mi = 0; mi < 2; mi++)
        #pragma unroll
        for (int hh = 0; hh < 2; hh++)
        #pragma unroll
        for (int ni = 0; ni < 8; ni++){
            int row = m0 + wm*32 + mi*16 + g + hh*8;
            int d = wn*64 + ni*8 + tq*2;
            int b = row >> nshift, n = row - (b << nshift);
            int wrd = ((d >> 5) << 4) + perm_w(d & 31);
            Yw[(size_t)((b*HEADS + h)*Nrows + n)*64 + wrd] =
                packh2(acc[mi][ni][hh*2] + bias[n0+d]*bsc, acc[mi][ni][hh*2+1] + bias[n0+d+1]*bsc);
        }
    } else {
        float* tr = (float*)smw;
        #pragma unroll
        for (int mi = 0; mi < 2; mi++)
        #pragma unroll
        for (int hh = 0; hh < 2; hh++)
        #pragma unroll
        for (int ni = 0; ni < 8; ni++)
        #pragma unroll
        for (int cc = 0; cc < 2; cc++){
            int rl = wm*32 + mi*16 + g + hh*8;
            int cl = wn*64 + ni*8 + tq*2 + cc;
            tr[cl*TRP + rl] = acc[mi][ni][hh*2+cc] + bias[n0+cl];
        }
        __syncthreads();
        int b = m0 >> nshift, nloc0 = m0 - (b << nshift);
        int cl = tid >> 1, half = tid & 1;
        uint32_t* Yw = (uint32_t*)Yout;
        uint32_t* dstrow = Yw + ((size_t)(b*HEADS + h)*DH + cl)*(size_t)(Nrows>>1) + (nloc0>>1);
        #pragma unroll
        for (int c2 = 0; c2 < 2; c2++){
            int chunk = half*2 + c2;
            const float* src = tr + cl*TRP + chunk*32;
            uint32_t wds[16];
            #pragma unroll
            for (int wd = 0; wd < 16; wd++){
                int j = wd >> 2, hi = (wd >> 1) & 1, s = wd & 1;
                int h0 = s*16 + hi*8 + 2*j;
                wds[wd] = packh2(src[h0], src[h0+1]);
            }
            uint32_t* dst = dstrow + chunk*16;
            #pragma unroll
            for (int qq = 0; qq < 4; qq++)
                ((uint4*)dst)[qq] = make_uint4(wds[qq*4], wds[qq*4+1], wds[qq*4+2], wds[qq*4+3]);
        }
    }
}

// ================= merged fused flash kernel (R11: 64-key stages, 2 buffers) =================
__global__ void __launch_bounds__(256, 2)
flash_kernel(){
    extern __shared__ uint32_t smw[];
    const __half *X, *Y, *VT; __half* Mid; int M, Nk, mb;
    if (blockIdx.x < 4){ X=g_u; Y=g_v; VT=g_pT; Mid=g_Pmid; M=NQ; Nk=NK; mb=blockIdx.x; }
    else               { X=g_v; Y=g_u; VT=g_gT; Mid=g_Dmid; M=NK; Nk=NQ; mb=blockIdx.x-4; }
    const int bh = blockIdx.y;
    const int m0 = mb * 128;
    const int tid = threadIdx.x, w = tid >> 5, lane = tid & 31;
    const int g = lane >> 2, tq = lane & 3;
    const int Nk2 = Nk >> 1;
    const int NT = Nk >> 6;
    const uint32_t* Xw = (const uint32_t*)(X + ((size_t)bh*M + m0)*DH);
    const uint32_t* Yw = (const uint32_t*)(Y + (size_t)bh*Nk*DH);
    const uint32_t* Vw = (const uint32_t*)(VT + (size_t)bh*DH*Nk);
    uint32_t sbase = (uint32_t)__cvta_generic_to_shared(smw);

    uint4 xa[4], xb[4];
    {
        const uint32_t* Xr = Xw + (size_t)(w*16 + g)*64 + tq*4;
        #pragma unroll
        for (int kk2 = 0; kk2 < 4; kk2++){
            xa[kk2] = *(const uint4*)(Xr + kk2*16);
            xb[kk2] = *(const uint4*)(Xr + 8*64 + kk2*16);
        }
    }

    const int yr = tid >> 4, ywq = tid & 15;
    const int pr2 = tid >> 3, pch = tid & 7;

    {
        #pragma unroll
        for (int i = 0; i < 4; i++){
            int r = yr + i*16;
            cpa16(sbase + (FLY0 + r*80 + ywq*4)*4, Yw + (size_t)r*64 + ywq*4);
        }
        #pragma unroll
        for (int i = 0; i < 4; i++){
            int r = pr2 + i*32;
            cpa16(sbase + (FLP0 + r*48 + pch*4)*4, Vw + (size_t)r*Nk2 + pch*4);
        }
        cpa_commit();
    }

    float acc[16][4] = {};
    float acc_rs[4] = {};
    int buf = 0;

    for (int kt = 0; kt < NT; kt++){
        cpa_wait0();
        __syncthreads();

        if (kt + 1 < NT){
            int yb = buf ? FLY0 : FLY1;
            int pb = buf ? FLP0 : FLP1;
            #pragma unroll
            for (int i = 0; i < 4; i++){
                int r = yr + i*16;
                cpa16(sbase + (yb + r*80 + ywq*4)*4, Yw + (size_t)((kt+1)*64 + r)*64 + ywq*4);
            }
            #pragma unroll
            for (int i = 0; i < 4; i++){
                int r = pr2 + i*32;
                cpa16(sbase + (pb + r*48 + pch*4)*4, Vw + (size_t)r*Nk2 + (kt+1)*32 + pch*4);
            }
            cpa_commit();
        }

        const uint32_t* Yb = smw + (buf ? FLY1 : FLY0);
        const uint32_t* Pb = smw + (buf ? FLP1 : FLP0);

        #pragma unroll
        for (int sub = 0; sub < 2; sub++){
            const uint32_t* Ys = Yb + sub*32*80;

            uint32_t eh[4][2];
            #pragma unroll
            for (int ni = 0; ni < 4; ni++){
                float cs[4] = {0.f, 0.f, 0.f, 0.f};
                #pragma unroll
                for (int kk2 = 0; kk2 < 4; kk2++){
                    uint4 r = *(const uint4*)(Ys + (ni*8 + g)*80 + kk2*16 + tq*4);
                    mma16h(cs, xa[kk2].x, xb[kk2].x, xa[kk2].z, xb[kk2].z, r.x, r.z);
                    mma16h(cs, xa[kk2].y, xb[kk2].y, xa[kk2].w, xb[kk2].w, r.y, r.w);
                }
                eh[ni][0] = ex2h2(packh2(cs[0], cs[1]));
                eh[ni][1] = ex2h2(packh2(cs[2], cs[3]));
            }

            mma16h(acc_rs, eh[0][0], eh[0][1], eh[1][0], eh[1][1], ONESW, ONESW);
            mma16h(acc_rs, eh[2][0], eh[2][1], eh[3][0], eh[3][1], ONESW, ONESW);

            #pragma unroll
            for (int n2 = 0; n2 < 16; n2++){
                uint4 r = *(const uint4*)(Pb + (n2*8 + g)*48 + sub*16 + tq*4);
                mma16h(acc[n2], eh[0][0], eh[0][1], eh[1][0], eh[1][1], r.x, r.z);
                mma16h(acc[n2], eh[2][0], eh[2][1], eh[3][0], eh[3][1], r.y, r.w);
            }
        }
        buf ^= 1;
    }

    float i0 = 1.0f / acc_rs[0], i1 = 1.0f / acc_rs[2];
    int b = bh >> 3, h = bh & 7;
    int mg = m0 + w*16 + g;
    uint32_t* o0 = (uint32_t*)Mid + (((size_t)(b*M + mg    )*HEADS + h) << 6);
    uint32_t* o8 = (uint32_t*)Mid + (((size_t)(b*M + mg + 8)*HEADS + h) << 6);
    #pragma unroll
    for (int n2 = 0; n2 < 16; n2++){
        int col = n2*8 + 2*tq;
        int wrd = ((col >> 5) << 4) + perm_w(col & 31);
        o0[wrd] = packh2(acc[n2][0]*i0, acc[n2][1]*i0);
        o8[wrd] = packh2(acc[n2][2]*i1, acc[n2][3]*i1);
    }
}

// ================= merged output projection (fp16 cp.async, 2-stage, 3 CTAs/SM) =================
__global__ void __launch_bounds__(256, 3)
outproj_kernel(const float* __restrict__ bo1, const float* __restrict__ bo2,
               float* __restrict__ out){
    __shared__ uint32_t As[2][128*16];
    __shared__ uint32_t Bs[2][64*16];
    const int bx = blockIdx.x;
    const bool isD = (bx >= 64);
    const int m0 = (isD ? bx - 64 : bx) * 128;
    const int n0 = blockIdx.y * 64;
    const __half* Xh = isD ? g_Dmid : g_Pmid;
    const __half* Wh = isD ? g_Wo2h : g_Wo1h;
    const float* bias = isD ? bo2 : bo1;
    float* outp = out + (isD ? (size_t)BATCH*NQ*DH : 0);
    const int tid = threadIdx.x, w = tid >> 5, lane = tid & 31;
    const int g = lane >> 2, tq = lane & 3;
    const int wm = w >> 1, wn = w & 1;
    const uint32_t* Xw = (const uint32_t*)Xh + (size_t)m0*512;
    const uint32_t* Ww = (const uint32_t*)Wh + (size_t)n0*512;
    uint32_t sa = (uint32_t)__cvta_generic_to_shared(&As[0][0]);
    uint32_t sb = (uint32_t)__cvta_generic_to_shared(&Bs[0][0]);

    float c[2][4][4] = {};
    {
        #pragma unroll
        for (int i = 0; i < 2; i++){
            int u = tid + i*256; int r = u >> 2, q = u & 3;
            cpa16(sa + (r*16 + q*4)*4, Xw + (size_t)r*512 + q*4);
        }
        { int r = tid >> 2, q = tid & 3;
          cpa16(sb + (r*16 + q*4)*4, Ww + (size_t)r*512 + q*4); }
        cpa_commit();
    }

    int buf = 0;
    for (int kt = 0; kt < 32; kt++){
        cpa_wait0();
        __syncthreads();
        if (kt + 1 < 32){
            int nb = buf ^ 1;
            #pragma unroll
            for (int i = 0; i < 2; i++){
                int u = tid + i*256; int r = u >> 2, q = u & 3;
                cpa16(sa + (nb*2048 + r*16 + q*4)*4, Xw + (size_t)r*512 + (kt+1)*16 + q*4);
            }
            { int r = tid >> 2, q = tid & 3;
              cpa16(sb + (nb*1024 + r*16 + q*4)*4, Ww + (size_t)r*512 + (kt+1)*16 + q*4); }
            cpa_commit();
        }
        const uint32_t* A = &As[buf][0];
        const uint32_t* B = &Bs[buf][0];
        uint4 xa[2], xb[2];
        #pragma unroll
        for (int mi = 0; mi < 2; mi++){
            xa[mi] = *(const uint4*)(A + (wm*32+mi*16+g)*16 + tq*4);
            xb[mi] = *(const uint4*)(A + (wm*32+mi*16+g+8)*16 + tq*4);
        }
        #pragma unroll
        for (int ni = 0; ni < 4; ni++){
            uint4 bb = *(const uint4*)(B + (wn*32+ni*8+g)*16 + tq*4);
            #pragma unroll
            for (int mi = 0; mi < 2; mi++){
                mma16h(c[mi][ni], xa[mi].x, xb[mi].x, xa[mi].z, xb[mi].z, bb.x, bb.z);
                mma16h(c[mi][ni], xa[mi].y, xb[mi].y, xa[mi].w, xb[mi].w, bb.y, bb.w);
            }
        }
        buf ^= 1;
    }

    #pragma unroll
    for (int mi=0;mi<2;mi++)
    #pragma unroll
    for (int hh=0;hh<2;hh++)
    #pragma unroll
    for (int ni=0;ni<4;ni++)
    #pragma unroll
    for (int cc=0;cc<2;cc++){
        int row = m0 + wm*32 + mi*16 + g + hh*8;
        int col = n0 + wn*32 + ni*8 + tq*2 + cc;
        outp[((size_t)row << 7) + col] = c[mi][ni][hh*2+cc] + bias[col];
    }
}

// ---------------- launch ----------------
extern "C" void kernel_launch(void* const* d_in, const int* in_sizes, int n_in,
                              void* d_out, int out_size){
    const float* queries = (const float*)d_in[0];
    const float* keys    = (const float*)d_in[1];
    const float* Wq  = (const float*)d_in[2];
    const float* bq  = (const float*)d_in[3];
    const float* Wk  = (const float*)d_in[4];
    const float* bk  = (const float*)d_in[5];
    const float* Wp  = (const float*)d_in[6];
    const float* bp  = (const float*)d_in[7];
    const float* Wg  = (const float*)d_in[8];
    const float* bg  = (const float*)d_in[9];
    const float* Wo1 = (const float*)d_in[10];
    const float* bo1 = (const float*)d_in[11];
    const float* Wo2 = (const float*)d_in[12];
    const float* bo2 = (const float*)d_in[13];
    float* out = (float*)d_out;

    cudaFuncSetAttribute(proj_kernel,  cudaFuncAttributeMaxDynamicSharedMemorySize, PRJ_BYTES);
    cudaFuncSetAttribute(flash_kernel, cudaFuncAttributeMaxDynamicSharedMemorySize, FL_BYTES);

    conv_all_kernel<<<dim3(4096, 8), 256>>>(queries, keys, Wq, Wk, Wp, Wg, Wo1, Wo2);

    proj_kernel<<<dim3(192, 16), 256, PRJ_BYTES>>>(bq, bk, bp, bg);

    flash_kernel<<<dim3(12, BH), 256, FL_BYTES>>>();

    outproj_kernel<<<dim3(192, 2), 256>>>(bo1, bo2, out);
}

// round 17
// speedup vs baseline: 1.0659x; 1.0342x over previous
#include <cuda_runtime.h>
#include <cuda_fp16.h>
#include <cstdint>
#include <cstddef>

// ---------------- problem constants ----------------
#define BATCH 16
#define NQ    512
#define NK    1024
#define DH    128
#define HEADS 8
#define BH    (BATCH*HEADS)        // 128
#define SC2   0.12751741254364243f // (1/sqrt(128)) * log2(e)  -- folded into Wq/bq
#define ONESW 0x3C003C00u          // fp16 (1.0, 1.0)

#define TRP 136
#define PRJ_BYTES ((128*80 + 128*80)*4)   // 81920

// flash smem layout (words): Y 2x(64x80), P 2x(128x48)
#define FLY0 0
#define FLY1 (64*80)
#define FLP0 (2*64*80)
#define FLP1 (FLP0 + 128*48)
#define FLW  (FLP1 + 128*48)
#define FL_BYTES (FLW*4)           // 90112

// ---------------- device scratch (fp16, perm32 along K dim) ----------------
__device__ __half g_qh [8192*DH];
__device__ __half g_kh [16384*DH];
__device__ __half g_Wqh[1024*DH];
__device__ __half g_Wkh[1024*DH];
__device__ __half g_Wph[1024*DH];
__device__ __half g_Wgh[1024*DH];
__device__ __half g_u  [(size_t)BH*NQ*DH];      // pre-scaled by SC2
__device__ __half g_v  [(size_t)BH*NK*DH];
__device__ __half g_pT [(size_t)BH*DH*NK];
__device__ __half g_gT [(size_t)BH*DH*NQ];
__device__ __half g_Pmid[(size_t)BATCH*NQ*HEADS*DH];
__device__ __half g_Dmid[(size_t)BATCH*NK*HEADS*DH];
__device__ __half g_Wo1h[128*1024];
__device__ __half g_Wo2h[128*1024];

// ---------------- helpers ----------------
__device__ __forceinline__ uint32_t packh2(float a, float b){
    __half2 h = __floats2half2_rn(a, b);
    return *reinterpret_cast<uint32_t*>(&h);
}
__device__ __forceinline__ uint32_t ex2h2(uint32_t x){
    uint32_t r;
    asm("ex2.approx.f16x2 %0, %1;" : "=r"(r) : "r"(x));
    return r;
}
__device__ __forceinline__ void mma16h(float (&c)[4], uint32_t a0, uint32_t a1, uint32_t a2, uint32_t a3,
                                       uint32_t b0, uint32_t b1){
    asm volatile("mma.sync.aligned.m16n8k16.row.col.f32.f16.f16.f32 "
        "{%0,%1,%2,%3}, {%4,%5,%6,%7}, {%8,%9}, {%0,%1,%2,%3};"
        : "+f"(c[0]),"+f"(c[1]),"+f"(c[2]),"+f"(c[3])
        : "r"(a0),"r"(a1),"r"(a2),"r"(a3), "r"(b0),"r"(b1));
}
__device__ __forceinline__ void cpa16(uint32_t dst_shared, const void* src){
    asm volatile("cp.async.cg.shared.global [%0], [%1], 16;" :: "r"(dst_shared), "l"(src));
}
__device__ __forceinline__ void cpa_commit(){ asm volatile("cp.async.commit_group;"); }
__device__ __forceinline__ void cpa_wait0(){ asm volatile("cp.async.wait_group 0;"); }
__device__ __forceinline__ void cpa_wait1(){ asm volatile("cp.async.wait_group 1;"); }

// perm32: word w of a 32-half chunk = j*4+hi*2+s holds halves (s*16+hi*8+2j, +1)
__device__ __forceinline__ int perm_w(int h32){
    int s = (h32 >> 4) & 1, hi = (h32 >> 3) & 1, j = (h32 & 7) >> 1;
    return j*4 + hi*2 + s;
}

// ================= conversion kernel: fp32 -> fp16 perm32 (exact grid) =================
// word ranges: q[0,524288) k[,1572864) Wq[,1638400) Wk[,1703936) Wp[,1769472)
//              Wg[,1835008) Wo1[,1900544) Wo2[,1966080)
__global__ void __launch_bounds__(256)
conv_all_kernel(const float* __restrict__ q, const float* __restrict__ k,
                const float* __restrict__ Wq, const float* __restrict__ Wk,
                const float* __restrict__ Wp, const float* __restrict__ Wg,
                const float* __restrict__ Wo1, const float* __restrict__ Wo2){
    int t = blockIdx.x*256 + threadIdx.x;
    const float* src; uint32_t* dst; int loc; bool wide = false; float sc = 1.0f;
    if (t < 1572864){
        if (t < 524288){ src = q; dst = (uint32_t*)g_qh; loc = t; }
        else           { src = k; dst = (uint32_t*)g_kh; loc = t - 524288; }
    } else if (t < 1835008){
        int u = t - 1572864;
        int wsel = u >> 16; loc = u & 65535;
        switch (wsel){
            case 0: src = Wq; dst = (uint32_t*)g_Wqh; sc = SC2; break;
            case 1: src = Wk; dst = (uint32_t*)g_Wkh; break;
            case 2: src = Wp; dst = (uint32_t*)g_Wph; break;
            default:src = Wg; dst = (uint32_t*)g_Wgh; break;
        }
    } else {
        int u = t - 1835008;
        wide = true;
        if (u < 65536){ src = Wo1; dst = (uint32_t*)g_Wo1h; loc = u; }
        else          { src = Wo2; dst = (uint32_t*)g_Wo2h; loc = u - 65536; }
    }
    int r, w9, rowfloats;
    if (!wide){ r = loc >> 6; w9 = loc & 63;  rowfloats = 128;  }
    else      { r = loc >> 9; w9 = loc & 511; rowfloats = 1024; }
    int chunk = w9 >> 4, wd = w9 & 15;
    int j = wd >> 2, hi = (wd >> 1) & 1, s = wd & 1;
    int k0 = chunk*32 + s*16 + hi*8 + 2*j;
    const float* sp = src + (size_t)r*rowfloats + k0;
    dst[(size_t)r*(rowfloats>>1) + w9] = packh2(sp[0]*sc, sp[1]*sc);
}

// ================= input projections (fp16 cp.async GEMM, split-K pipeline) =================
__global__ void __launch_bounds__(256)
proj_kernel(const float* __restrict__ bq, const float* __restrict__ bk,
            const float* __restrict__ bp, const float* __restrict__ bg){
    extern __shared__ uint32_t smw[];
    const int bx = blockIdx.x;
    const bool isK = (bx >= 64);
    const int m0 = (isK ? bx - 64 : bx) * 128;
    const int trans = blockIdx.y >> 3;
    const int n0 = (blockIdx.y & 7) * 128;
    const __half* Xh  = isK ? g_kh : g_qh;
    const __half* Wh  = trans ? (isK ? g_Wph : g_Wgh) : (isK ? g_Wkh : g_Wqh);
    const float* bias = trans ? (isK ? bp : bg) : (isK ? bk : bq);
    __half* Yout      = trans ? (isK ? g_pT : g_gT) : (isK ? g_v : g_u);
    const float bsc   = (!isK && !trans) ? SC2 : 1.0f;
    const int Nrows   = isK ? NK : NQ;
    const int nshift  = isK ? 10 : 9;
    const int tid = threadIdx.x, w = tid >> 5, lane = tid & 31;
    const int g = lane >> 2, tq = lane & 3;
    const int wm = w >> 1, wn = w & 1;

    uint32_t sx = (uint32_t)__cvta_generic_to_shared(smw);
    uint32_t sw = sx + 10240*4;
    const uint32_t* Xw = (const uint32_t*)Xh + (size_t)m0*64;
    const uint32_t* Ww = (const uint32_t*)Wh + (size_t)n0*64;

    // chunk A: quads 0-7 (kk 0-1)
    #pragma unroll
    for (int i = 0; i < 4; i++){
        int id = tid + i*256;                // 0..1023
        int r = id >> 3, wq = id & 7;
        cpa16(sx + (r*80 + wq*4)*4, Xw + (size_t)r*64 + wq*4);
        cpa16(sw + (r*80 + wq*4)*4, Ww + (size_t)r*64 + wq*4);
    }
    cpa_commit();
    // chunk B: quads 8-15 (kk 2-3)
    #pragma unroll
    for (int i = 0; i < 4; i++){
        int id = tid + i*256;
        int r = id >> 3, wq = (id & 7) + 8;
        cpa16(sx + (r*80 + wq*4)*4, Xw + (size_t)r*64 + wq*4);
        cpa16(sw + (r*80 + wq*4)*4, Ww + (size_t)r*64 + wq*4);
    }
    cpa_commit();

    float acc[2][8][4] = {};
    const uint32_t* Xs = smw;
    const uint32_t* Ws = smw + 10240;

    cpa_wait1();
    __syncthreads();
    #pragma unroll
    for (int kk = 0; kk < 2; kk++){
        uint4 xa[2], xb[2];
        #pragma unroll
        for (int mi = 0; mi < 2; mi++){
            xa[mi] = *(const uint4*)(Xs + (wm*32+mi*16+g)*80 + kk*16 + tq*4);
            xb[mi] = *(const uint4*)(Xs + (wm*32+mi*16+g+8)*80 + kk*16 + tq*4);
        }
        #pragma unroll
        for (int ni = 0; ni < 8; ni++){
            uint4 bb = *(const uint4*)(Ws + (wn*64+ni*8+g)*80 + kk*16 + tq*4);
            #pragma unroll
            for (int mi = 0; mi < 2; mi++){
                mma16h(acc[mi][ni], xa[mi].x, xb[mi].x, xa[mi].z, xb[mi].z, bb.x, bb.z);
                mma16h(acc[mi][ni], xa[mi].y, xb[mi].y, xa[mi].w, xb[mi].w, bb.y, bb.w);
            }
        }
    }
    cpa_wait0();
    __syncthreads();
    #pragma unroll
    for (int kk = 2; kk < 4; kk++){
        uint4 xa[2], xb[2];
        #pragma unroll
        for (int mi = 0; mi < 2; mi++){
            xa[mi] = *(const uint4*)(Xs + (wm*32+mi*16+g)*80 + kk*16 + tq*4);
            xb[mi] = *(const uint4*)(Xs + (wm*32+mi*16+g+8)*80 + kk*16 + tq*4);
        }
        #pragma unroll
        for (int ni = 0; ni < 8; ni++){
            uint4 bb = *(const uint4*)(Ws + (wn*64+ni*8+g)*80 + kk*16 + tq*4);
            #pragma unroll
            for (int mi = 0; mi < 2; mi++){
                mma16h(acc[mi][ni], xa[mi].x, xb[mi].x, xa[mi].z, xb[mi].z, bb.x, bb.z);
                mma16h(acc[mi][ni], xa[mi].y, xb[mi].y, xa[mi].w, xb[mi].w, bb.y, bb.w);
            }
        }
    }
    __syncthreads();

    const int h = n0 >> 7;
    if (!trans){
        uint32_t* Yw = (uint32_t*)Yout;
        #pragma unroll
        for (int mi = 0; mi < 2; mi++)
        #pragma unroll
        for (int hh = 0; hh < 2; hh++)
        #pragma unroll
        for (int ni = 0; ni < 8; ni++){
            int row = m0 + wm*32 + mi*16 + g + hh*8;
            int d = wn*64 + ni*8 + tq*2;
            int b = row >> nshift, n = row - (b << nshift);
            int wrd = ((d >> 5) << 4) + perm_w(d & 31);
            Yw[(size_t)((b*HEADS + h)*Nrows + n)*64 + wrd] =
                packh2(acc[mi][ni][hh*2] + bias[n0+d]*bsc, acc[mi][ni][hh*2+1] + bias[n0+d+1]*bsc);
        }
    } else {
        float* tr = (float*)smw;
        #pragma unroll
        for (int mi = 0; mi < 2; mi++)
        #pragma unroll
        for (int hh = 0; hh < 2; hh++)
        #pragma unroll
        for (int ni = 0; ni < 8; ni++)
        #pragma unroll
        for (int cc = 0; cc < 2; cc++){
            int rl = wm*32 + mi*16 + g + hh*8;
            int cl = wn*64 + ni*8 + tq*2 + cc;
            tr[cl*TRP + rl] = acc[mi][ni][hh*2+cc] + bias[n0+cl];
        }
        __syncthreads();
        int b = m0 >> nshift, nloc0 = m0 - (b << nshift);
        int cl = tid >> 1, half = tid & 1;
        uint32_t* Yw = (uint32_t*)Yout;
        uint32_t* dstrow = Yw + ((size_t)(b*HEADS + h)*DH + cl)*(size_t)(Nrows>>1) + (nloc0>>1);
        #pragma unroll
        for (int c2 = 0; c2 < 2; c2++){
            int chunk = half*2 + c2;
            const float* src = tr + cl*TRP + chunk*32;
            uint32_t wds[16];
            #pragma unroll
            for (int wd = 0; wd < 16; wd++){
                int j = wd >> 2, hi = (wd >> 1) & 1, s = wd & 1;
                int h0 = s*16 + hi*8 + 2*j;
                wds[wd] = packh2(src[h0], src[h0+1]);
            }
            uint32_t* dst = dstrow + chunk*16;
            #pragma unroll
            for (int qq = 0; qq < 4; qq++)
                ((uint4*)dst)[qq] = make_uint4(wds[qq*4], wds[qq*4+1], wds[qq*4+2], wds[qq*4+3]);
        }
    }
}

// ================= merged fused flash kernel (R11: 64-key stages, 2 buffers) =================
__global__ void __launch_bounds__(256, 2)
flash_kernel(){
    extern __shared__ uint32_t smw[];
    const __half *X, *Y, *VT; __half* Mid; int M, Nk, mb;
    if (blockIdx.x < 4){ X=g_u; Y=g_v; VT=g_pT; Mid=g_Pmid; M=NQ; Nk=NK; mb=blockIdx.x; }
    else               { X=g_v; Y=g_u; VT=g_gT; Mid=g_Dmid; M=NK; Nk=NQ; mb=blockIdx.x-4; }
    const int bh = blockIdx.y;
    const int m0 = mb * 128;
    const int tid = threadIdx.x, w = tid >> 5, lane = tid & 31;
    const int g = lane >> 2, tq = lane & 3;
    const int Nk2 = Nk >> 1;
    const int NT = Nk >> 6;
    const uint32_t* Xw = (const uint32_t*)(X + ((size_t)bh*M + m0)*DH);
    const uint32_t* Yw = (const uint32_t*)(Y + (size_t)bh*Nk*DH);
    const uint32_t* Vw = (const uint32_t*)(VT + (size_t)bh*DH*Nk);
    uint32_t sbase = (uint32_t)__cvta_generic_to_shared(smw);

    uint4 xa[4], xb[4];
    {
        const uint32_t* Xr = Xw + (size_t)(w*16 + g)*64 + tq*4;
        #pragma unroll
        for (int kk2 = 0; kk2 < 4; kk2++){
            xa[kk2] = *(const uint4*)(Xr + kk2*16);
            xb[kk2] = *(const uint4*)(Xr + 8*64 + kk2*16);
        }
    }

    const int yr = tid >> 4, ywq = tid & 15;
    const int pr2 = tid >> 3, pch = tid & 7;

    {
        #pragma unroll
        for (int i = 0; i < 4; i++){
            int r = yr + i*16;
            cpa16(sbase + (FLY0 + r*80 + ywq*4)*4, Yw + (size_t)r*64 + ywq*4);
        }
        #pragma unroll
        for (int i = 0; i < 4; i++){
            int r = pr2 + i*32;
            cpa16(sbase + (FLP0 + r*48 + pch*4)*4, Vw + (size_t)r*Nk2 + pch*4);
        }
        cpa_commit();
    }

    float acc[16][4] = {};
    float acc_rs[4] = {};
    int buf = 0;

    for (int kt = 0; kt < NT; kt++){
        cpa_wait0();
        __syncthreads();

        if (kt + 1 < NT){
            int yb = buf ? FLY0 : FLY1;
            int pb = buf ? FLP0 : FLP1;
            #pragma unroll
            for (int i = 0; i < 4; i++){
                int r = yr + i*16;
                cpa16(sbase + (yb + r*80 + ywq*4)*4, Yw + (size_t)((kt+1)*64 + r)*64 + ywq*4);
            }
            #pragma unroll
            for (int i = 0; i < 4; i++){
                int r = pr2 + i*32;
                cpa16(sbase + (pb + r*48 + pch*4)*4, Vw + (size_t)r*Nk2 + (kt+1)*32 + pch*4);
            }
            cpa_commit();
        }

        const uint32_t* Yb = smw + (buf ? FLY1 : FLY0);
        const uint32_t* Pb = smw + (buf ? FLP1 : FLP0);

        #pragma unroll
        for (int sub = 0; sub < 2; sub++){
            const uint32_t* Ys = Yb + sub*32*80;

            uint32_t eh[4][2];
            #pragma unroll
            for (int ni = 0; ni < 4; ni++){
                float cs[4] = {0.f, 0.f, 0.f, 0.f};
                #pragma unroll
                for (int kk2 = 0; kk2 < 4; kk2++){
                    uint4 r = *(const uint4*)(Ys + (ni*8 + g)*80 + kk2*16 + tq*4);
                    mma16h(cs, xa[kk2].x, xb[kk2].x, xa[kk2].z, xb[kk2].z, r.x, r.z);
                    mma16h(cs, xa[kk2].y, xb[kk2].y, xa[kk2].w, xb[kk2].w, r.y, r.w);
                }
                eh[ni][0] = ex2h2(packh2(cs[0], cs[1]));
                eh[ni][1] = ex2h2(packh2(cs[2], cs[3]));
            }

            mma16h(acc_rs, eh[0][0], eh[0][1], eh[1][0], eh[1][1], ONESW, ONESW);
            mma16h(acc_rs, eh[2][0], eh[2][1], eh[3][0], eh[3][1], ONESW, ONESW);

            #pragma unroll
            for (int n2 = 0; n2 < 16; n2++){
                uint4 r = *(const uint4*)(Pb + (n2*8 + g)*48 + sub*16 + tq*4);
                mma16h(acc[n2], eh[0][0], eh[0][1], eh[1][0], eh[1][1], r.x, r.z);
                mma16h(acc[n2], eh[2][0], eh[2][1], eh[3][0], eh[3][1], r.y, r.w);
            }
        }
        buf ^= 1;
    }

    float i0 = 1.0f / acc_rs[0], i1 = 1.0f / acc_rs[2];
    int b = bh >> 3, h = bh & 7;
    int mg = m0 + w*16 + g;
    uint32_t* o0 = (uint32_t*)Mid + (((size_t)(b*M + mg    )*HEADS + h) << 6);
    uint32_t* o8 = (uint32_t*)Mid + (((size_t)(b*M + mg + 8)*HEADS + h) << 6);
    #pragma unroll
    for (int n2 = 0; n2 < 16; n2++){
        int col = n2*8 + 2*tq;
        int wrd = ((col >> 5) << 4) + perm_w(col & 31);
        o0[wrd] = packh2(acc[n2][0]*i0, acc[n2][1]*i0);
        o8[wrd] = packh2(acc[n2][2]*i1, acc[n2][3]*i1);
    }
}

// ================= merged output projection (fp16 cp.async, 2-stage, 3 CTAs/SM) =================
__global__ void __launch_bounds__(256, 3)
outproj_kernel(const float* __restrict__ bo1, const float* __restrict__ bo2,
               float* __restrict__ out){
    __shared__ uint32_t As[2][128*16];
    __shared__ uint32_t Bs[2][64*16];
    const int bx = blockIdx.x;
    const bool isD = (bx >= 64);
    const int m0 = (isD ? bx - 64 : bx) * 128;
    const int n0 = blockIdx.y * 64;
    const __half* Xh = isD ? g_Dmid : g_Pmid;
    const __half* Wh = isD ? g_Wo2h : g_Wo1h;
    const float* bias = isD ? bo2 : bo1;
    float* outp = out + (isD ? (size_t)BATCH*NQ*DH : 0);
    const int tid = threadIdx.x, w = tid >> 5, lane = tid & 31;
    const int g = lane >> 2, tq = lane & 3;
    const int wm = w >> 1, wn = w & 1;
    const uint32_t* Xw = (const uint32_t*)Xh + (size_t)m0*512;
    const uint32_t* Ww = (const uint32_t*)Wh + (size_t)n0*512;
    uint32_t sa = (uint32_t)__cvta_generic_to_shared(&As[0][0]);
    uint32_t sb = (uint32_t)__cvta_generic_to_shared(&Bs[0][0]);

    float c[2][4][4] = {};
    {
        #pragma unroll
        for (int i = 0; i < 2; i++){
            int u = tid + i*256; int r = u >> 2, q = u & 3;
            cpa16(sa + (r*16 + q*4)*4, Xw + (size_t)r*512 + q*4);
        }
        { int r = tid >> 2, q = tid & 3;
          cpa16(sb + (r*16 + q*4)*4, Ww + (size_t)r*512 + q*4); }
        cpa_commit();
    }

    int buf = 0;
    for (int kt = 0; kt < 32; kt++){
        cpa_wait0();
        __syncthreads();
        if (kt + 1 < 32){
            int nb = buf ^ 1;
            #pragma unroll
            for (int i = 0; i < 2; i++){
                int u = tid + i*256; int r = u >> 2, q = u & 3;
                cpa16(sa + (nb*2048 + r*16 + q*4)*4, Xw + (size_t)r*512 + (kt+1)*16 + q*4);
            }
            { int r = tid >> 2, q = tid & 3;
              cpa16(sb + (nb*1024 + r*16 + q*4)*4, Ww + (size_t)r*512 + (kt+1)*16 + q*4); }
            cpa_commit();
        }
        const uint32_t* A = &As[buf][0];
        const uint32_t* B = &Bs[buf][0];
        uint4 xa[2], xb[2];
        #pragma unroll
        for (int mi = 0; mi < 2; mi++){
            xa[mi] = *(const uint4*)(A + (wm*32+mi*16+g)*16 + tq*4);
            xb[mi] = *(const uint4*)(A + (wm*32+mi*16+g+8)*16 + tq*4);
        }
        #pragma unroll
        for (int ni = 0; ni < 4; ni++){
            uint4 bb = *(const uint4*)(B + (wn*32+ni*8+g)*16 + tq*4);
            #pragma unroll
            for (int mi = 0; mi < 2; mi++){
                mma16h(c[mi][ni], xa[mi].x, xb[mi].x, xa[mi].z, xb[mi].z, bb.x, bb.z);
                mma16h(c[mi][ni], xa[mi].y, xb[mi].y, xa[mi].w, xb[mi].w, bb.y, bb.w);
            }
        }
        buf ^= 1;
    }

    #pragma unroll
    for (int mi=0;mi<2;mi++)
    #pragma unroll
    for (int hh=0;hh<2;hh++)
    #pragma unroll
    for (int ni=0;ni<4;ni++)
    #pragma unroll
    for (int cc=0;cc<2;cc++){
        int row = m0 + wm*32 + mi*16 + g + hh*8;
        int col = n0 + wn*32 + ni*8 + tq*2 + cc;
        outp[((size_t)row << 7) + col] = c[mi][ni][hh*2+cc] + bias[col];
    }
}

// ---------------- launch ----------------
extern "C" void kernel_launch(void* const* d_in, const int* in_sizes, int n_in,
                              void* d_out, int out_size){
    const float* queries = (const float*)d_in[0];
    const float* keys    = (const float*)d_in[1];
    const float* Wq  = (const float*)d_in[2];
    const float* bq  = (const float*)d_in[3];
    const float* Wk  = (const float*)d_in[4];
    const float* bk  = (const float*)d_in[5];
    const float* Wp  = (const float*)d_in[6];
    const float* bp  = (const float*)d_in[7];
    const float* Wg  = (const float*)d_in[8];
    const float* bg  = (const float*)d_in[9];
    const float* Wo1 = (const float*)d_in[10];
    const float* bo1 = (const float*)d_in[11];
    const float* Wo2 = (const float*)d_in[12];
    const float* bo2 = (const float*)d_in[13];
    float* out = (float*)d_out;

    cudaFuncSetAttribute(proj_kernel,  cudaFuncAttributeMaxDynamicSharedMemorySize, PRJ_BYTES);
    cudaFuncSetAttribute(flash_kernel, cudaFuncAttributeMaxDynamicSharedMemorySize, FL_BYTES);

    conv_all_kernel<<<7680, 256>>>(queries, keys, Wq, Wk, Wp, Wg, Wo1, Wo2);

    proj_kernel<<<dim3(192, 16), 256, PRJ_BYTES>>>(bq, bk, bp, bg);

    flash_kernel<<<dim3(12, BH), 256, FL_BYTES>>>();

    outproj_kernel<<<dim3(192, 2), 256>>>(bo1, bo2, out);
}